// round 16
// baseline (speedup 1.0000x reference)
#include <cuda_runtime.h>
#include <cstdint>

#define BB 8
#define NN 2048
#define FF 256
#define ALPHA 0.2f
#define JT 32
#define NT (NN / JT)

// Scratch (allocation-free rule: __device__ globals)
__device__ float g_Whr[BB * NN * FF];   // tf32-rounded Wh (attn B operand)
__device__ float g_WT[FF * FF];         // W transposed [k][o]
__device__ float g_s1[BB * NN];
__device__ float g_s2[BB * NN];

__device__ __forceinline__ float to_tf32(float x) {
    uint32_t r; asm("cvt.rna.tf32.f32 %0, %1;" : "=r"(r) : "f"(x));
    return __uint_as_float(r);
}
__device__ __forceinline__ void cp_async16(uint32_t dst, const void* src) {
    asm volatile("cp.async.cg.shared.global [%0], [%1], 16;" :: "r"(dst), "l"(src));
}
#define CP_COMMIT() asm volatile("cp.async.commit_group;" ::: "memory")
#define CP_WAIT0()  asm volatile("cp.async.wait_group 0;" ::: "memory")
#define CP_WAIT1()  asm volatile("cp.async.wait_group 1;" ::: "memory")

__device__ __forceinline__ void mma_tf32(float* d,
                                         uint32_t a0, uint32_t a1, uint32_t a2, uint32_t a3,
                                         uint32_t b0, uint32_t b1) {
    asm volatile("mma.sync.aligned.m16n8k8.row.col.f32.tf32.tf32.f32 "
                 "{%0,%1,%2,%3}, {%4,%5,%6,%7}, {%8,%9}, {%0,%1,%2,%3};"
                 : "+f"(d[0]), "+f"(d[1]), "+f"(d[2]), "+f"(d[3])
                 : "r"(a0), "r"(a1), "r"(a2), "r"(a3), "r"(b0), "r"(b1));
}

// ---------------------------------------------------------------------------
// K0: transpose W [F_OUT, F_IN] -> g_WT [F_IN, F_OUT]
// ---------------------------------------------------------------------------
__global__ void transpose_W(const float* __restrict__ W) {
    __shared__ float tile[32][33];
    int k0 = blockIdx.x * 32;
    int o0 = blockIdx.y * 32;
    int lx = threadIdx.x & 31;
    int ly = threadIdx.x >> 5;
#pragma unroll
    for (int s = 0; s < 32; s += 8)
        tile[ly + s][lx] = W[(o0 + ly + s) * FF + (k0 + lx)];
    __syncthreads();
#pragma unroll
    for (int s = 0; s < 32; s += 8)
        g_WT[(k0 + ly + s) * FF + (o0 + lx)] = tile[lx][ly + s];
}

// ---------------------------------------------------------------------------
// K1: Wh = h @ W^T via tf32 mma.sync (R15-proven) + fused s1/s2 epilogue.
// ---------------------------------------------------------------------------
#define HS_STRIDE 36
#define WS_STRIDE 264

__global__ __launch_bounds__(256) void gemm_Wh(const float* __restrict__ h,
                                               const float* __restrict__ a) {
    __shared__ float hs[64 * HS_STRIDE];
    __shared__ float ws[32 * WS_STRIDE];
    __shared__ float s1s[64], s2s[64];
    const int row0 = blockIdx.x * 64;
    const int t = threadIdx.x;
    const int w = t >> 5;
    const int lane = t & 31;
    const int gid = lane >> 2, tig = lane & 3;
    const int nbase = w * 32;

    if (t < 64) { s1s[t] = 0.0f; s2s[t] = 0.0f; }

    float d[4][4][4];
#pragma unroll
    for (int rg = 0; rg < 4; rg++)
#pragma unroll
        for (int nt = 0; nt < 4; nt++)
#pragma unroll
            for (int c = 0; c < 4; c++) d[rg][nt][c] = 0.0f;

    for (int kt = 0; kt < 8; kt++) {
        __syncthreads();
#pragma unroll
        for (int s = 0; s < 2; s++) {
            int v = t + 256 * s;
            int row = v >> 3, c4 = v & 7;
            float4 x = *(const float4*)(h + (size_t)(row0 + row) * FF + kt * 32 + c4 * 4);
            x.x = to_tf32(x.x); x.y = to_tf32(x.y);
            x.z = to_tf32(x.z); x.w = to_tf32(x.w);
            *(float4*)&hs[row * HS_STRIDE + c4 * 4] = x;
        }
#pragma unroll
        for (int s = 0; s < 8; s++) {
            int v = t + 256 * s;
            int kk = v >> 6, c4 = v & 63;
            float4 x = *(const float4*)(g_WT + (size_t)(kt * 32 + kk) * FF + c4 * 4);
            x.x = to_tf32(x.x); x.y = to_tf32(x.y);
            x.z = to_tf32(x.z); x.w = to_tf32(x.w);
            *(float4*)&ws[kk * WS_STRIDE + c4 * 4] = x;
        }
        __syncthreads();

        const uint32_t* hsu = (const uint32_t*)hs;
        const uint32_t* wsu = (const uint32_t*)ws;
#pragma unroll
        for (int kk = 0; kk < 4; kk++) {
            const int k = kk * 8;
            uint32_t bv[4][2];
            const uint32_t* brow0 = wsu + (k + tig) * WS_STRIDE + nbase + gid;
            const uint32_t* brow1 = wsu + (k + 4 + tig) * WS_STRIDE + nbase + gid;
#pragma unroll
            for (int nt = 0; nt < 4; nt++) {
                bv[nt][0] = brow0[nt * 8];
                bv[nt][1] = brow1[nt * 8];
            }
#pragma unroll
            for (int rg = 0; rg < 4; rg++) {
                const int ra = rg * 16 + gid;
                uint32_t a0 = hsu[ra * HS_STRIDE + k + tig];
                uint32_t a1 = hsu[(ra + 8) * HS_STRIDE + k + tig];
                uint32_t a2 = hsu[ra * HS_STRIDE + k + 4 + tig];
                uint32_t a3 = hsu[(ra + 8) * HS_STRIDE + k + 4 + tig];
#pragma unroll
                for (int nt = 0; nt < 4; nt++)
                    mma_tf32(d[rg][nt], a0, a1, a2, a3, bv[nt][0], bv[nt][1]);
            }
        }
    }

#pragma unroll
    for (int rg = 0; rg < 4; rg++) {
        const int ra = rg * 16 + gid;
        float p1A = 0.0f, p2A = 0.0f, p1B = 0.0f, p2B = 0.0f;
#pragma unroll
        for (int nt = 0; nt < 4; nt++) {
            int col = nbase + nt * 8 + 2 * tig;
            float a10 = a[col], a11 = a[col + 1];
            float a20 = a[FF + col], a21 = a[FF + col + 1];
            p1A += d[rg][nt][0] * a10 + d[rg][nt][1] * a11;
            p2A += d[rg][nt][0] * a20 + d[rg][nt][1] * a21;
            p1B += d[rg][nt][2] * a10 + d[rg][nt][3] * a11;
            p2B += d[rg][nt][2] * a20 + d[rg][nt][3] * a21;
            *(float2*)(g_Whr + (size_t)(row0 + ra) * FF + col) =
                make_float2(to_tf32(d[rg][nt][0]), to_tf32(d[rg][nt][1]));
            *(float2*)(g_Whr + (size_t)(row0 + ra + 8) * FF + col) =
                make_float2(to_tf32(d[rg][nt][2]), to_tf32(d[rg][nt][3]));
        }
        p1A += __shfl_xor_sync(0xffffffffu, p1A, 1);
        p1A += __shfl_xor_sync(0xffffffffu, p1A, 2);
        p2A += __shfl_xor_sync(0xffffffffu, p2A, 1);
        p2A += __shfl_xor_sync(0xffffffffu, p2A, 2);
        p1B += __shfl_xor_sync(0xffffffffu, p1B, 1);
        p1B += __shfl_xor_sync(0xffffffffu, p1B, 2);
        p2B += __shfl_xor_sync(0xffffffffu, p2B, 1);
        p2B += __shfl_xor_sync(0xffffffffu, p2B, 2);
        if (tig == 0) {
            atomicAdd(&s1s[ra], p1A);
            atomicAdd(&s2s[ra], p2A);
            atomicAdd(&s1s[ra + 8], p1B);
            atomicAdd(&s2s[ra + 8], p2B);
        }
    }
    __syncthreads();
    if (t < 64) {
        g_s1[row0 + t] = s1s[t];
        g_s2[row0 + t] = s2s[t];
    }
}

// ---------------------------------------------------------------------------
// K3: attention. R11/R15 pipeline, but ps stored as paired-k float2s
// (p[j], p[j+4]) so A-fragments load via LDS.64 (halves A-frag LDS count).
// ps row stride = 20 float2 (conflict-free: banks 8*gid+2*tig distinct).
// smem: whs[2] 67584 B, ps2[2] 20480 B, s2a 8192 B, ls 256 B = 96512 B.
// ---------------------------------------------------------------------------
#define WHS_STRIDE 264
#define PS2_STRIDE 20
#define WHS_BYTES  (JT * WHS_STRIDE * 4)
#define PS_BYTES   (64 * PS2_STRIDE * 8)
#define SMEM_WHS   0
#define SMEM_PS    (2 * WHS_BYTES)
#define SMEM_S2    (SMEM_PS + 2 * PS_BYTES)
#define SMEM_LS    (SMEM_S2 + NN * 4)
#define SMEM_TOTAL (SMEM_LS + 64 * 4)

__global__ __launch_bounds__(256, 2) void attn(const int* __restrict__ adj,
                                               float* __restrict__ out) {
    extern __shared__ char smem[];
    float* s2a = (float*)(smem + SMEM_S2);
    float* ls  = (float*)(smem + SMEM_LS);
    uint32_t smem_u32;
    { uint64_t tmp; asm("cvta.to.shared.u64 %0, %1;" : "=l"(tmp) : "l"(smem));
      smem_u32 = (uint32_t)tmp; }

    const int b  = blockIdx.y;
    const int i0 = blockIdx.x * 64;
    const int t  = threadIdx.x;
    const int w  = t >> 5;
    const int lane = t & 31;
    const int gid  = lane >> 2;
    const int tig  = lane & 3;
    const int nbase = w * 32;

    const int arow = t >> 2;
    const int ajl  = (t & 3) * 8;        // this thread's 8-j group (one kk group)
    const int akk  = t & 3;              // its kk index
    const float s1v = g_s1[(size_t)b * NN + i0 + arow];
    const int* adjrow = adj + ((size_t)b * NN + i0 + arow) * NN;
    const float* whr_b = g_Whr + (size_t)b * NN * FF;

    ((float4*)s2a)[t]       = ((const float4*)(g_s2 + (size_t)b * NN))[t];
    ((float4*)s2a)[t + 256] = ((const float4*)(g_s2 + (size_t)b * NN))[t + 256];
    if (t < 64) ls[t] = 0.0f;

    float d[4][4][4];
#pragma unroll
    for (int rg = 0; rg < 4; rg++)
#pragma unroll
        for (int nt = 0; nt < 4; nt++)
#pragma unroll
            for (int c = 0; c < 4; c++) d[rg][nt][c] = 0.0f;

    // ---- prologue: issue whs(0) + adj(0); A(0) after barrier ----
    {
#pragma unroll
        for (int s = 0; s < 8; s++) {
            int v = t + 256 * s;
            int row = v >> 6, c = (v & 63) * 4;
            cp_async16(smem_u32 + SMEM_WHS + (row * WHS_STRIDE + c) * 4,
                       whr_b + (size_t)row * FF + c);
        }
        CP_COMMIT();
    }
    int4 av[2];
#pragma unroll
    for (int q = 0; q < 2; q++) av[q] = *(const int4*)(adjrow + ajl + q * 4);
    __syncthreads();

    // stage A(0) -> ps buf 0 (paired-k layout)
    {
        float* psc = (float*)(smem + SMEM_PS);
        float pv[8];
        float psum = 0.0f;
#pragma unroll
        for (int q = 0; q < 2; q++) {
            int ad[4] = {av[q].x, av[q].y, av[q].z, av[q].w};
#pragma unroll
            for (int s = 0; s < 4; s++) {
                float x = s1v + s2a[ajl + q * 4 + s];
                float e = (x > 0.0f) ? x : ALPHA * x;
                float p = ad[s] ? __expf(e) : 0.0f;
                psum += p;
                pv[q * 4 + s] = to_tf32(p);
            }
        }
        float* dst = psc + (arow * PS2_STRIDE + akk * 4) * 2;
        *(float4*)(dst)     = make_float4(pv[0], pv[4], pv[1], pv[5]);
        *(float4*)(dst + 4) = make_float4(pv[2], pv[6], pv[3], pv[7]);
        psum += __shfl_xor_sync(0xffffffffu, psum, 1);
        psum += __shfl_xor_sync(0xffffffffu, psum, 2);
        if ((t & 3) == 0) ls[arow] += psum;
    }

    for (int tile = 0; tile < NT; tile++) {
        const int cur = tile & 1;

        __syncthreads();

        const bool more = (tile + 1 < NT);
        if (more) {
            const int jn = (tile + 1) * JT;
#pragma unroll
            for (int s = 0; s < 8; s++) {
                int v = t + 256 * s;
                int row = v >> 6, c = (v & 63) * 4;
                cp_async16(smem_u32 + SMEM_WHS + (cur ^ 1) * WHS_BYTES +
                               (row * WHS_STRIDE + c) * 4,
                           whr_b + (size_t)(jn + row) * FF + c);
            }
            CP_COMMIT();
#pragma unroll
            for (int q = 0; q < 2; q++)
                av[q] = *(const int4*)(adjrow + jn + ajl + q * 4);
            CP_WAIT1();
        } else {
            CP_WAIT0();
        }

        // ---- stage B: tensor-core PV, LDS.64 A-fragments ----
        const float2* psu2 = (const float2*)(smem + SMEM_PS + cur * PS_BYTES);
        const uint32_t* whsu = (const uint32_t*)(smem + SMEM_WHS + cur * WHS_BYTES);
#pragma unroll
        for (int kk = 0; kk < 4; kk++) {
            const int k = kk * 8;
            uint32_t bv[4][2];
            const uint32_t* brow0 = whsu + (k + tig) * WHS_STRIDE + nbase + gid;
            const uint32_t* brow1 = whsu + (k + 4 + tig) * WHS_STRIDE + nbase + gid;
#pragma unroll
            for (int nt = 0; nt < 4; nt++) {
                bv[nt][0] = brow0[nt * 8];
                bv[nt][1] = brow1[nt * 8];
            }
#pragma unroll
            for (int rg = 0; rg < 4; rg++) {
                const int ra = rg * 16 + gid;
                float2 vA = psu2[ra * PS2_STRIDE + kk * 4 + tig];        // (a0, a2)
                float2 vB = psu2[(ra + 8) * PS2_STRIDE + kk * 4 + tig];  // (a1, a3)
                uint32_t a0 = __float_as_uint(vA.x);
                uint32_t a2 = __float_as_uint(vA.y);
                uint32_t a1 = __float_as_uint(vB.x);
                uint32_t a3 = __float_as_uint(vB.y);
#pragma unroll
                for (int nt = 0; nt < 4; nt++)
                    mma_tf32(d[rg][nt], a0, a1, a2, a3, bv[nt][0], bv[nt][1]);
            }
        }

        // ---- stage A(tile+1) ----
        if (more) {
            const int jn = (tile + 1) * JT;
            float* psc = (float*)(smem + SMEM_PS + (cur ^ 1) * PS_BYTES);
            float pv[8];
            float psum = 0.0f;
#pragma unroll
            for (int q = 0; q < 2; q++) {
                int ad[4] = {av[q].x, av[q].y, av[q].z, av[q].w};
#pragma unroll
                for (int s = 0; s < 4; s++) {
                    float x = s1v + s2a[jn + ajl + q * 4 + s];
                    float e = (x > 0.0f) ? x : ALPHA * x;
                    float p = ad[s] ? __expf(e) : 0.0f;
                    psum += p;
                    pv[q * 4 + s] = to_tf32(p);
                }
            }
            float* dst = psc + (arow * PS2_STRIDE + akk * 4) * 2;
            *(float4*)(dst)     = make_float4(pv[0], pv[4], pv[1], pv[5]);
            *(float4*)(dst + 4) = make_float4(pv[2], pv[6], pv[3], pv[7]);
            psum += __shfl_xor_sync(0xffffffffu, psum, 1);
            psum += __shfl_xor_sync(0xffffffffu, psum, 2);
            if ((t & 3) == 0) ls[arow] += psum;
        }
    }

    __syncthreads();

#pragma unroll
    for (int rg = 0; rg < 4; rg++) {
        const int ra = rg * 16 + gid;
        float inva = 1.0f / ls[ra];
        float invb = 1.0f / ls[ra + 8];
        float* outa = out + ((size_t)b * NN + i0 + ra) * FF;
        float* outb = outa + (size_t)8 * FF;
#pragma unroll
        for (int nt = 0; nt < 4; nt++) {
            int col = nbase + nt * 8 + 2 * tig;
            *(float2*)(outa + col) = make_float2(d[rg][nt][0] * inva, d[rg][nt][1] * inva);
            *(float2*)(outb + col) = make_float2(d[rg][nt][2] * invb, d[rg][nt][3] * invb);
        }
    }
}

// ---------------------------------------------------------------------------
extern "C" void kernel_launch(void* const* d_in, const int* in_sizes, int n_in,
                              void* d_out, int out_size) {
    const float* h   = (const float*)d_in[0];
    const int*   adj = (const int*)d_in[1];
    const float* W   = (const float*)d_in[2];
    const float* a   = (const float*)d_in[3];
    float* out = (float*)d_out;

    cudaFuncSetAttribute(attn, cudaFuncAttributeMaxDynamicSharedMemorySize, SMEM_TOTAL);

    transpose_W<<<dim3(FF / 32, FF / 32), 256>>>(W);
    gemm_Wh<<<(BB * NN) / 64, 256>>>(h, a);
    attn<<<dim3(NN / 64, BB), 256, SMEM_TOTAL>>>(adj, out);
}